// round 2
// baseline (speedup 1.0000x reference)
#include <cuda_runtime.h>

#define FX 64
#define H_DIM 256
#define FOUT 64
#define XW 132   // 128 + 4 pad (floats)
#define HW 260   // 256 + 4 pad (floats)

// Precomputed u[b] @ W1[128:192] + b1 : [512, 256]
__device__ float g_ubb[512 * H_DIM];

__global__ void ubb_kernel(const float* __restrict__ u,
                           const float* __restrict__ W1,
                           const float* __restrict__ b1, int B) {
    __shared__ float us[FX];
    int b = blockIdx.x;
    int c = threadIdx.x;            // 0..255
    if (c < FX) us[c] = u[b * FX + c];
    __syncthreads();
    float acc = b1[c];
#pragma unroll 16
    for (int k = 0; k < FX; ++k)
        acc = fmaf(us[k], W1[(2 * FX + k) * H_DIM + c], acc);
    g_ubb[b * H_DIM + c] = acc;
}

__global__ __launch_bounds__(256, 2)
void edge_mlp_kernel(const float* __restrict__ src,
                     const float* __restrict__ dst,
                     const int* __restrict__ batch,   // int32 graph ids
                     const float* __restrict__ W1,
                     const float* __restrict__ W2,
                     const float* __restrict__ b2,
                     float* __restrict__ out, int E, int B)
{
    extern __shared__ float sm[];
    float* xs  = sm;                 // [64][132]  dest|src tile
    float* hs  = xs + 64 * XW;       // [64][260]  hidden (starts as ubb)
    float* ws  = hs + 64 * HW;       // [2048]     weight staging
    float* b2s = ws + 2048;          // [64]
    int*   bs  = (int*)(b2s + 64);   // [64]

    const int tid   = threadIdx.x;
    const int ebase = blockIdx.x * 64;
    const int tx = tid & 15;
    const int ty = tid >> 4;         // 0..15

    if (tid < 64) {
        int e = ebase + tid;
        int b = (e < E) ? batch[e] : 0;
        if (b < 0) b = 0;
        if (b >= B) b = B - 1;       // safety clamp: never fault on bad dtype
        bs[tid]  = b;
        b2s[tid] = b2[tid];
    }
    __syncthreads();

    // ---- stage x = [dest | src] tile (zero-padded tail) ----
    {
        const float4* d4 = (const float4*)dst;
        const float4* s4 = (const float4*)src;
#pragma unroll
        for (int t = 0; t < 8; ++t) {
            int idx = tid + t * 256;          // 0..2047
            int r = idx >> 5;                 // row 0..63
            int q = idx & 31;                 // float4 slot 0..31
            long e = ebase + r;
            float4 v = make_float4(0.f, 0.f, 0.f, 0.f);
            if (e < E)
                v = (q < 16) ? d4[e * 16 + q] : s4[e * 16 + (q - 16)];
            float* p = xs + r * XW + q * 4;
            p[0] = v.x; p[1] = v.y; p[2] = v.z; p[3] = v.w;
        }
        // ---- stage hs with ubb[batch[e]] (includes b1) ----
#pragma unroll 4
        for (int r = 0; r < 64; ++r)
            hs[r * HW + tid] = g_ubb[bs[r] * H_DIM + tid];
    }

    // ---- phase 2: h = [dest|src] @ W1[0:128]  (64x256, K=128) ----
    float acc[4][16];
#pragma unroll
    for (int i = 0; i < 4; ++i)
#pragma unroll
        for (int j = 0; j < 16; ++j) acc[i][j] = 0.f;

    for (int k0 = 0; k0 < 128; k0 += 8) {
        __syncthreads();
#pragma unroll
        for (int t = 0; t < 8; ++t)                  // W1 chunk: 8 rows x 256
            ws[t * 256 + tid] = W1[(k0 + t) * H_DIM + tid];
        __syncthreads();
#pragma unroll
        for (int kk = 0; kk < 8; ++kk) {
            float a[4], b[16];
#pragma unroll
            for (int i = 0; i < 4; ++i) a[i] = xs[(ty + 16 * i) * XW + k0 + kk];
#pragma unroll
            for (int j = 0; j < 16; ++j) b[j] = ws[kk * 256 + tx + 16 * j];
#pragma unroll
            for (int i = 0; i < 4; ++i)
#pragma unroll
                for (int j = 0; j < 16; ++j)
                    acc[i][j] = fmaf(a[i], b[j], acc[i][j]);
        }
    }

    // epilogue: relu(acc + ubb) -> hs (each thread owns its cells)
#pragma unroll
    for (int i = 0; i < 4; ++i)
#pragma unroll
        for (int j = 0; j < 16; ++j) {
            int r = ty + 16 * i, c = tx + 16 * j;
            float v = acc[i][j] + hs[r * HW + c];
            hs[r * HW + c] = fmaxf(v, 0.f);
        }

    // ---- phase 3: out = h @ W2 + b2  (64x64, K=256) ----
    float acc2[4][4];
#pragma unroll
    for (int i = 0; i < 4; ++i)
#pragma unroll
        for (int j = 0; j < 4; ++j) acc2[i][j] = 0.f;

    for (int k0 = 0; k0 < 256; k0 += 16) {
        __syncthreads();                             // also fences hs epilogue on first iter
#pragma unroll
        for (int t = 0; t < 4; ++t) {
            int idx = tid + t * 256;                 // 0..1023 = kk*64 + c
            ws[idx] = W2[k0 * FOUT + idx];
        }
        __syncthreads();
#pragma unroll
        for (int kk = 0; kk < 16; ++kk) {
            float a[4], b[4];
#pragma unroll
            for (int i = 0; i < 4; ++i) a[i] = hs[(ty + 16 * i) * HW + k0 + kk];
#pragma unroll
            for (int j = 0; j < 4; ++j) b[j] = ws[kk * 64 + tx + 16 * j];
#pragma unroll
            for (int i = 0; i < 4; ++i)
#pragma unroll
                for (int j = 0; j < 4; ++j)
                    acc2[i][j] = fmaf(a[i], b[j], acc2[i][j]);
        }
    }

#pragma unroll
    for (int i = 0; i < 4; ++i) {
        int r = ty + 16 * i;
        long e = ebase + r;
        if (e < E) {
#pragma unroll
            for (int j = 0; j < 4; ++j) {
                int c = tx + 16 * j;
                out[e * FOUT + c] = acc2[i][j] + b2s[c];
            }
        }
    }
}

extern "C" void kernel_launch(void* const* d_in, const int* in_sizes, int n_in,
                              void* d_out, int out_size) {
    const float* src   = (const float*)d_in[0];
    const float* dest  = (const float*)d_in[1];
    /* d_in[2] = edge_attr, unused by the reference MLP input */
    const float* u     = (const float*)d_in[3];
    const int*   batch = (const int*)d_in[4];    // int32 (JAX x64 disabled)
    const float* W1    = (const float*)d_in[5];
    const float* b1    = (const float*)d_in[6];
    const float* W2    = (const float*)d_in[7];
    const float* b2    = (const float*)d_in[8];
    float* out = (float*)d_out;

    int E = in_sizes[4];        // batch has one entry per edge
    int B = in_sizes[3] / FX;   // 512

    ubb_kernel<<<B, 256>>>(u, W1, b1, B);

    size_t smem = (size_t)(64 * XW + 64 * HW + 2048 + 64) * sizeof(float)
                + 64 * sizeof(int);
    cudaFuncSetAttribute(edge_mlp_kernel,
                         cudaFuncAttributeMaxDynamicSharedMemorySize, (int)smem);
    int grid = (E + 63) / 64;
    edge_mlp_kernel<<<grid, 256, smem>>>(src, dest, batch, W1, W2, b2, out, E, B);
}

// round 4
// speedup vs baseline: 4.3672x; 4.3672x over previous
#include <cuda_runtime.h>
#include <cuda_bf16.h>
#include <stdint.h>

#define FXD 64
#define HD 256
#define NTHR 256

// ---- Precomputed u[b]@W1[128:192] + b1 : [512,256] fp32 ----
__device__ __align__(16) float g_ubb[512 * HD];

__global__ void ubb_kernel(const float* __restrict__ u,
                           const float* __restrict__ W1,
                           const float* __restrict__ b1) {
    __shared__ float us[FXD];
    int b = blockIdx.x, c = threadIdx.x;
    if (c < FXD) us[c] = u[b * FXD + c];
    __syncthreads();
    float acc = b1[c];
#pragma unroll 16
    for (int k = 0; k < FXD; ++k)
        acc = fmaf(us[k], W1[(2 * FXD + k) * HD + c], acc);
    g_ubb[b * HD + c] = acc;
}

__device__ __forceinline__ void split2(float a, float b, uint32_t& hi, uint32_t& lo) {
    __nv_bfloat162 h = __float22bfloat162_rn(make_float2(a, b));  // lo=a, hi=b
    hi = *reinterpret_cast<uint32_t*>(&h);
    float ra = a - __bfloat162float(h.x);
    float rb = b - __bfloat162float(h.y);
    __nv_bfloat162 l = __float22bfloat162_rn(make_float2(ra, rb));
    lo = *reinterpret_cast<uint32_t*>(&l);
}

__device__ __forceinline__ void mma16816(float* c, const uint32_t* a,
                                         uint32_t b0, uint32_t b1) {
    asm volatile(
        "mma.sync.aligned.m16n8k16.row.col.f32.bf16.bf16.f32 "
        "{%0,%1,%2,%3}, {%4,%5,%6,%7}, {%8,%9}, {%0,%1,%2,%3};"
        : "+f"(c[0]), "+f"(c[1]), "+f"(c[2]), "+f"(c[3])
        : "r"(a[0]), "r"(a[1]), "r"(a[2]), "r"(a[3]), "r"(b0), "r"(b1));
}

// SMEM layout (uint4 units):
//   w1s: [8 kstep][32 ntile][32 lane] uint4{hi0,hi1,lo0,lo1}  = 8192 uint4 (128KB)
//   w2s: [16 kstep][8 ntile][32 lane] uint4                   = 4096 uint4 (64KB)
//   b2s: 64 floats
#define W2_OFF  8192
#define B2_OFF  (8192 + 4096)
#define SMEM_SZ ((8192 + 4096) * 16 + 256)

__global__ __launch_bounds__(NTHR, 1)
void edge_mlp_hmma(const float* __restrict__ src,
                   const float* __restrict__ dst,
                   const int* __restrict__ batch,
                   const float* __restrict__ W1,
                   const float* __restrict__ W2,
                   const float* __restrict__ b2,
                   float* __restrict__ out, int E, int B)
{
    extern __shared__ uint4 smem4[];
    uint4* w1s = smem4;
    uint4* w2s = smem4 + W2_OFF;
    float* b2s = (float*)(smem4 + B2_OFF);

    const int tid  = threadIdx.x;
    const int wid  = tid >> 5;
    const int lane = tid & 31;
    const int gg   = lane >> 2;   // group row
    const int tig  = lane & 3;    // thread in group

    // ---- stage W1 as B-fragments, hi/lo bf16 split ----
    for (int i = tid; i < 8 * 32 * 32 * 2; i += NTHR) {
        int p = i & 1, t = (i >> 1) & 31, nt = (i >> 6) & 31, s = (i >> 11);
        int k0 = s * 16 + 2 * (t & 3) + p * 8;
        int n  = nt * 8 + (t >> 2);
        float w0 = W1[k0 * HD + n], w1 = W1[(k0 + 1) * HD + n];
        uint32_t hi, lo; split2(w0, w1, hi, lo);
        uint32_t* cell = (uint32_t*)&w1s[(s * 32 + nt) * 32 + t];
        cell[p] = hi; cell[2 + p] = lo;
    }
    // ---- stage W2 ----
    for (int i = tid; i < 16 * 8 * 32 * 2; i += NTHR) {
        int p = i & 1, t = (i >> 1) & 31, nt = (i >> 6) & 7, s = (i >> 9);
        int k0 = s * 16 + 2 * (t & 3) + p * 8;
        int n  = nt * 8 + (t >> 2);
        float w0 = W2[k0 * 64 + n], w1 = W2[(k0 + 1) * 64 + n];
        uint32_t hi, lo; split2(w0, w1, hi, lo);
        uint32_t* cell = (uint32_t*)&w2s[(s * 8 + nt) * 32 + t];
        cell[p] = hi; cell[2 + p] = lo;
    }
    if (tid < 64) b2s[tid] = b2[tid];
    __syncthreads();

    const int ntiles = (E + 127) >> 7;

    for (long tile = blockIdx.x; tile < ntiles; tile += gridDim.x) {
        const long e0 = tile * 128 + wid * 16 + gg;
        const long e1 = e0 + 8;
        const bool v0 = e0 < (long)E;
        const bool v1 = e1 < (long)E;
        int b0i = v0 ? batch[e0] : 0; b0i = min(max(b0i, 0), B - 1);
        int b1i = v1 ? batch[e1] : 0; b1i = min(max(b1i, 0), B - 1);

        // ---- load A1 fragments (x = [dest|src]) hi/lo ----
        uint32_t Ah[8][4], Al[8][4];
#pragma unroll
        for (int s = 0; s < 8; ++s) {
            const float* xp = (s < 4) ? dst : src;
            const int k = (s & 3) * 16 + 2 * tig;
            float2 z = make_float2(0.f, 0.f);
            float2 p00 = v0 ? *(const float2*)(xp + e0 * 64 + k)     : z;
            float2 p01 = v0 ? *(const float2*)(xp + e0 * 64 + k + 8) : z;
            float2 p10 = v1 ? *(const float2*)(xp + e1 * 64 + k)     : z;
            float2 p11 = v1 ? *(const float2*)(xp + e1 * 64 + k + 8) : z;
            split2(p00.x, p00.y, Ah[s][0], Al[s][0]);
            split2(p10.x, p10.y, Ah[s][1], Al[s][1]);
            split2(p01.x, p01.y, Ah[s][2], Al[s][2]);
            split2(p11.x, p11.y, Ah[s][3], Al[s][3]);
        }

        float C2[32];
#pragma unroll
        for (int i = 0; i < 32; ++i) C2[i] = 0.f;

#pragma unroll 1
        for (int c1 = 0; c1 < 4; ++c1) {
            // ---- GEMM1 chunk: C1[16 x 64] over K=128, 3 passes ----
            float C1[32];
#pragma unroll
            for (int i = 0; i < 32; ++i) C1[i] = 0.f;
#pragma unroll
            for (int s = 0; s < 8; ++s) {
#pragma unroll
                for (int nt = 0; nt < 8; ++nt) {
                    uint4 wv = w1s[(s * 32 + c1 * 8 + nt) * 32 + lane];
                    mma16816(C1 + nt * 4, Ah[s], wv.x, wv.y);   // hi*hi
                    mma16816(C1 + nt * 4, Ah[s], wv.z, wv.w);   // hi*lo
                    mma16816(C1 + nt * 4, Al[s], wv.x, wv.y);   // lo*hi
                }
            }

            // ---- epilogue: + ubb, relu, repack C1 -> A2 fragments ----
            uint32_t A2h[4][4], A2l[4][4];
            const float* u0 = g_ubb + (size_t)b0i * HD + c1 * 64;
            const float* u1 = g_ubb + (size_t)b1i * HD + c1 * 64;
#pragma unroll
            for (int nt = 0; nt < 8; ++nt) {
                float2 ua = *(const float2*)(u0 + nt * 8 + 2 * tig);
                float2 ub = *(const float2*)(u1 + nt * 8 + 2 * tig);
                float f0 = fmaxf(C1[nt * 4 + 0] + ua.x, 0.f);
                float f1 = fmaxf(C1[nt * 4 + 1] + ua.y, 0.f);
                float f2 = fmaxf(C1[nt * 4 + 2] + ub.x, 0.f);
                float f3 = fmaxf(C1[nt * 4 + 3] + ub.y, 0.f);
                uint32_t h01, l01, h23, l23;
                split2(f0, f1, h01, l01);
                split2(f2, f3, h23, l23);
                const int q = nt >> 1, r = (nt & 1) * 2;
                A2h[q][r + 0] = h01; A2h[q][r + 1] = h23;
                A2l[q][r + 0] = l01; A2l[q][r + 1] = l23;
            }

            // ---- GEMM2 partial: C2 += h_chunk @ W2[k-chunk] ----
#pragma unroll
            for (int q = 0; q < 4; ++q) {
#pragma unroll
                for (int nt2 = 0; nt2 < 8; ++nt2) {
                    uint4 wv = w2s[((c1 * 4 + q) * 8 + nt2) * 32 + lane];
                    mma16816(C2 + nt2 * 4, A2h[q], wv.x, wv.y);
                    mma16816(C2 + nt2 * 4, A2h[q], wv.z, wv.w);
                    mma16816(C2 + nt2 * 4, A2l[q], wv.x, wv.y);
                }
            }
        }

        // ---- store out = C2 + b2 ----
#pragma unroll
        for (int nt2 = 0; nt2 < 8; ++nt2) {
            const int col = nt2 * 8 + 2 * tig;
            if (v0) {
                float2 o;
                o.x = C2[nt2 * 4 + 0] + b2s[col];
                o.y = C2[nt2 * 4 + 1] + b2s[col + 1];
                *(float2*)(out + e0 * 64 + col) = o;
            }
            if (v1) {
                float2 o;
                o.x = C2[nt2 * 4 + 2] + b2s[col];
                o.y = C2[nt2 * 4 + 3] + b2s[col + 1];
                *(float2*)(out + e1 * 64 + col) = o;
            }
        }
    }
}

extern "C" void kernel_launch(void* const* d_in, const int* in_sizes, int n_in,
                              void* d_out, int out_size) {
    const float* src   = (const float*)d_in[0];
    const float* dest  = (const float*)d_in[1];
    /* d_in[2] = edge_attr, unused by the reference */
    const float* u     = (const float*)d_in[3];
    const int*   batch = (const int*)d_in[4];
    const float* W1    = (const float*)d_in[5];
    const float* b1    = (const float*)d_in[6];
    const float* W2    = (const float*)d_in[7];
    const float* b2    = (const float*)d_in[8];
    float* out = (float*)d_out;

    int E = in_sizes[4];
    int B = in_sizes[3] / FXD;

    ubb_kernel<<<B, 256>>>(u, W1, b1);

    int nsm = 148;
    cudaDeviceGetAttribute(&nsm, cudaDevAttrMultiProcessorCount, 0);
    int ntiles = (E + 127) >> 7;
    int grid = nsm < ntiles ? nsm : ntiles;

    cudaFuncSetAttribute(edge_mlp_hmma,
                         cudaFuncAttributeMaxDynamicSharedMemorySize, SMEM_SZ);
    edge_mlp_hmma<<<grid, NTHR, SMEM_SZ>>>(src, dest, batch, W1, W2, b2, out, E, B);
}